// round 7
// baseline (speedup 1.0000x reference)
#include <cuda_runtime.h>
#include <cuda_bf16.h>
#include <math.h>
#include <stdint.h>

// ---------------- problem constants ----------------
#define QN      40000
#define NCAM    6
#define IMGW    480.0f
#define IMGH    224.0f

// level geometry
#define HW0 6720
#define HW1 1680
#define HW2 420
#define HW3 105
#define TOTPIX 8925

// scratch buffers
__device__ float g_tf[(size_t)TOTPIX * NCAM * 128];          // 27.4 MB transposed features
__device__ float g_fvec[(size_t)QN * 1024];                   // 163.8 MB
__device__ float g_h1[(size_t)QN * 512];                      // 81.9 MB
__device__ float g_h2[(size_t)QN * 512];                      // 81.9 MB
__device__ float g_w1[1024 * 512];                            // tf32-rounded weights
__device__ float g_w2[512 * 512];
__device__ float g_w3[512 * 512];
__device__ float g_w4[512 * 128];

__device__ __forceinline__ uint32_t f2tf(float x) {
    uint32_t u;
    asm("cvt.rna.tf32.f32 %0, %1;" : "=r"(u) : "f"(x));
    return u;
}
__device__ __forceinline__ float rnatf(float x) {
    return __uint_as_float(f2tf(x));
}
__device__ __forceinline__ void cp16(uint32_t dst, const void* src, bool ok) {
    int sz = ok ? 16 : 0;
    asm volatile("cp.async.cg.shared.global [%0], [%1], 16, %2;"
                 :: "r"(dst), "l"(src), "r"(sz));
}

// ---------------- fused tf32 weight rounding (one launch) ----------------
#define W1N (1024 * 512)
#define W2N (512 * 512)
#define W3N (512 * 512)
#define W4N (512 * 128)
__global__ void round_all_kernel(const float* __restrict__ c1, const float* __restrict__ c2,
                                 const float* __restrict__ c3, const float* __restrict__ c4) {
    int i = blockIdx.x * 256 + threadIdx.x;
    if (i < W1N) {
        g_w1[i] = rnatf(c1[i]);
    } else if (i < W1N + W2N) {
        int j = i - W1N; g_w2[j] = rnatf(c2[j]);
    } else if (i < W1N + W2N + W3N) {
        int j = i - W1N - W2N; g_w3[j] = rnatf(c3[j]);
    } else if (i < W1N + W2N + W3N + W4N) {
        int j = i - W1N - W2N - W3N; g_w4[j] = rnatf(c4[j]);
    }
}

// ---------------- fused feat transpose (one launch, all 4 levels) ----------------
// [n][128ch][HW] -> level-blocked [n][HW][128]
__global__ void transpose_all_kernel(const float* __restrict__ f0, const float* __restrict__ f1,
                                     const float* __restrict__ f2, const float* __restrict__ f3) {
    __shared__ float s[32][33];
    // tile thresholds: level0 210 tiles, l1 53, l2 14, l3 4 (cum 210,263,277,281)
    int t = blockIdx.x;
    int level, trel;
    const float* feat;
    int HW; size_t lbase;
    if (t < 210)      { level = 0; trel = t;        feat = f0; HW = HW0; lbase = 0; }
    else if (t < 263) { level = 1; trel = t - 210;  feat = f1; HW = HW1; lbase = (size_t)HW0 * NCAM * 128; }
    else if (t < 277) { level = 2; trel = t - 263;  feat = f2; HW = HW2; lbase = (size_t)(HW0 + HW1) * NCAM * 128; }
    else              { level = 3; trel = t - 277;  feat = f3; HW = HW3; lbase = (size_t)(HW0 + HW1 + HW2) * NCAM * 128; }
    (void)level;

    int n    = blockIdx.z;
    int ch0  = blockIdx.y * 32;
    int pix0 = trel * 32;
    int tx = threadIdx.x, ty = threadIdx.y;

    int pix = pix0 + tx;
    int ch  = ch0 + ty;
    if (pix < HW)
        s[ty][tx] = feat[((size_t)(n * 128 + ch)) * HW + pix];
    __syncthreads();
    int pixw = pix0 + ty;
    int chw  = ch0 + tx;
    if (pixw < HW)
        g_tf[lbase + ((size_t)n * HW + pixw) * 128 + chw] = s[tx][ty];
}

// ---------------- sampling + scale softmax + projection ----------------
__global__ __launch_bounds__(128) void sample_kernel(
    const float* __restrict__ query,   // [Q][P][128]
    const float* __restrict__ qpos,    // [Z=8][Q][3]
    const float* __restrict__ l2i,     // [6][4][4]
    const float* __restrict__ Wsw,     // [128][16]
    const float* __restrict__ bsw)     // [16]
{
    __shared__ __align__(16) float s_q[1024];
    __shared__ __align__(16) float s_wsw[2048];
    __shared__ float s_logit[128];
    __shared__ float s_sw[128];
    __shared__ float s_bsw[16];
    __shared__ float s_l2i[96];
    __shared__ float s_qp[8][3];
    __shared__ float s_u[8], s_v[8];
    __shared__ int   s_cam[8], s_ok[8];

    const int q   = blockIdx.x;
    const int tid = threadIdx.x;

    {
        const float4* qv = (const float4*)(query + (size_t)q * 1024);
        float4* d = (float4*)s_q;
        d[tid] = qv[tid]; d[tid + 128] = qv[tid + 128];

        const float4* wv = (const float4*)Wsw;
        float4* sw4 = (float4*)s_wsw;
        sw4[tid] = wv[tid]; sw4[tid + 128] = wv[tid + 128];
        sw4[tid + 256] = wv[tid + 256]; sw4[tid + 384] = wv[tid + 384];

        if (tid < 16) s_bsw[tid] = bsw[tid];
        if (tid < 96) s_l2i[tid] = l2i[tid];
        if (tid < 24) s_qp[tid / 3][tid % 3] = qpos[((size_t)(tid / 3) * QN + q) * 3 + (tid % 3)];
    }
    __syncthreads();

    // scale-weight logits
    {
        int p = tid >> 4, gl = tid & 15;
        float acc = s_bsw[gl];
        const float* qrow = s_q + p * 128;
        #pragma unroll 8
        for (int k = 0; k < 128; k++) acc += qrow[k] * s_wsw[k * 16 + gl];
        s_logit[tid] = acc;
    }
    // projection: first valid camera per point
    if (tid < 8) {
        int p = tid;
        float X = s_qp[p][0] * 100.f - 50.f;
        float Y = s_qp[p][1] * 100.f - 50.f;
        float Zc = s_qp[p][2] * 8.f - 4.f;
        int found = 0, cam = 0; float uu = 0.f, vv = 0.f;
        #pragma unroll
        for (int n = 0; n < 6; n++) {
            const float* M = s_l2i + n * 16;
            float c0 = M[0] * X + M[1] * Y + M[2]  * Zc + M[3];
            float c1 = M[4] * X + M[5] * Y + M[6]  * Zc + M[7];
            float c2 = M[8] * X + M[9] * Y + M[10] * Zc + M[11];
            float den = fmaxf(c2, 1e-6f);
            float u = (c0 / den) / IMGW;
            float v = (c1 / den) / IMGH;
            bool val = (c2 > 1e-6f) && (u > 0.f) && (u < 1.f) && (v > 0.f) && (v < 1.f);
            if (val && !found) { found = 1; cam = n; uu = u; vv = v; }
        }
        s_cam[p] = cam; s_ok[p] = found; s_u[p] = uu; s_v[p] = vv;
    }
    __syncthreads();

    // softmax over levels per (p,g)
    if (tid < 32) {
        int base = tid * 4;
        float a = s_logit[base], b = s_logit[base + 1], c = s_logit[base + 2], d = s_logit[base + 3];
        float m = fmaxf(fmaxf(a, b), fmaxf(c, d));
        float ea = expf(a - m), eb = expf(b - m), ec = expf(c - m), ed = expf(d - m);
        float inv = 1.f / (ea + eb + ec + ed);
        s_sw[base] = ea * inv; s_sw[base + 1] = eb * inv;
        s_sw[base + 2] = ec * inv; s_sw[base + 3] = ed * inv;
    }
    __syncthreads();

    const int cch = tid;
    const int LW[4]    = {120, 60, 30, 15};
    const int LH[4]    = {56, 28, 14, 7};
    const int LHW[4]   = {HW0, HW1, HW2, HW3};
    const int LBASE[4] = {0, HW0 * NCAM * 128, (HW0 + HW1) * NCAM * 128, (HW0 + HW1 + HW2) * NCAM * 128};

    const int g = cch >> 5;
    float* outp = g_fvec + (size_t)q * 1024 + cch;

    #pragma unroll 1
    for (int p = 0; p < 8; p++) {
        float sval = 0.f;
        if (s_ok[p]) {
            int cam = s_cam[p];
            float u = s_u[p], v = s_v[p];
            const float* swp = s_sw + p * 16 + g * 4;
            #pragma unroll
            for (int l = 0; l < 4; l++) {
                int w = LW[l], h = LH[l];
                const float* base = g_tf + LBASE[l] + (size_t)cam * LHW[l] * 128;
                float x = u * (float)w - 0.5f;
                float y = v * (float)h - 0.5f;
                float xf = floorf(x), yf = floorf(y);
                float wx = x - xf, wy = y - yf;
                int x0 = (int)xf, y0 = (int)yf;
                int x1 = x0 + 1, y1 = y0 + 1;
                bool ix0 = (x0 >= 0) && (x0 < w);
                bool ix1 = (x1 < w);
                bool iy0 = (y0 >= 0) && (y0 < h);
                bool iy1 = (y1 < h);
                float v00 = (iy0 && ix0) ? base[((size_t)y0 * w + x0) * 128 + cch] : 0.f;
                float v01 = (iy0 && ix1) ? base[((size_t)y0 * w + x1) * 128 + cch] : 0.f;
                float v10 = (iy1 && ix0) ? base[((size_t)y1 * w + x0) * 128 + cch] : 0.f;
                float v11 = (iy1 && ix1) ? base[((size_t)y1 * w + x1) * 128 + cch] : 0.f;
                float bil = v00 * (1.f - wx) * (1.f - wy) + v01 * wx * (1.f - wy)
                          + v10 * (1.f - wx) * wy + v11 * wx * wy;
                sval += bil * swp[l];
            }
        }
        outp[p * 128] = sval;
    }
}

// ---------------- tf32 GEMM v5: 3-stage cp.async, 128 thr, 64x64 warp tiles, occ 2 ----------------
// A and W must already be tf32-rounded (rna). grid = (N/128, ceil(M/128)).
#define ASZ (128 * 36)
#define BSZ (32 * 136)
#define STG (ASZ + BSZ)
#define NSTAGE 3

template <int RELU, int ROUND>
__global__ __launch_bounds__(128, 2) void mma_gemm5(
    const float* __restrict__ A, const float* __restrict__ W,
    const float* __restrict__ bias, float* __restrict__ C,
    int M, int K, int N)
{
    extern __shared__ uint32_t sm[];

    const int tid  = threadIdx.x;
    const int lane = tid & 31;
    const int warp = tid >> 5;        // 0..3
    const int wm = warp >> 1;         // 0..1 (64 rows)
    const int wn = warp & 1;          // 0..1 (64 cols)
    const int bn = blockIdx.x * 128, bm = blockIdx.y * 128;

    float c[4][8][4];
    #pragma unroll
    for (int i = 0; i < 4; i++)
        #pragma unroll
        for (int j = 0; j < 8; j++) {
            c[i][j][0] = 0.f; c[i][j][1] = 0.f; c[i][j][2] = 0.f; c[i][j][3] = 0.f;
        }

    uint32_t as_base[NSTAGE], bs_base[NSTAGE];
    #pragma unroll
    for (int s = 0; s < NSTAGE; s++) {
        as_base[s] = (uint32_t)__cvta_generic_to_shared(sm + s * STG);
        bs_base[s] = (uint32_t)__cvta_generic_to_shared(sm + s * STG + ASZ);
    }

    auto load_slab = [&](int k0, int s) {
        #pragma unroll
        for (int i = 0; i < 8; i++) {
            int idx = tid + 128 * i;
            int row = idx >> 3, kq = idx & 7;
            bool ok = (bm + row) < M;
            const float* src = A + (size_t)(bm + (ok ? row : 0)) * K + k0 + kq * 4;
            cp16(as_base[s] + (row * 36 + kq * 4) * 4, src, ok);
        }
        #pragma unroll
        for (int i = 0; i < 8; i++) {
            int idx = tid + 128 * i;
            int kr = idx >> 5, nq = idx & 31;
            const float* src = W + (size_t)(k0 + kr) * N + bn + nq * 4;
            cp16(bs_base[s] + (kr * 136 + nq * 4) * 4, src, true);
        }
    };

    const int nslab = K >> 5;
    load_slab(0, 0);
    asm volatile("cp.async.commit_group;");
    load_slab(32, 1);
    asm volatile("cp.async.commit_group;");

    for (int i = 0; i < nslab; i++) {
        asm volatile("cp.async.wait_group 1;");
        __syncthreads();

        if (i + 2 < nslab) load_slab((i + 2) << 5, (i + 2) % NSTAGE);
        asm volatile("cp.async.commit_group;");

        const int s = i % NSTAGE;
        const uint32_t* As = sm + s * STG;
        const uint32_t* Bs = sm + s * STG + ASZ;

        #pragma unroll
        for (int kt = 0; kt < 4; kt++) {
            const int kk = kt * 8 + (lane & 3);
            uint32_t a[4][4], b[8][2];
            const int mrow = wm * 64 + (lane >> 2);
            #pragma unroll
            for (int mt = 0; mt < 4; mt++) {
                int m = mrow + mt * 16;
                a[mt][0] = As[m * 36 + kk];
                a[mt][1] = As[(m + 8) * 36 + kk];
                a[mt][2] = As[m * 36 + kk + 4];
                a[mt][3] = As[(m + 8) * 36 + kk + 4];
            }
            const int nc = wn * 64 + (lane >> 2);
            #pragma unroll
            for (int nt = 0; nt < 8; nt++) {
                int n = nc + nt * 8;
                b[nt][0] = Bs[kk * 136 + n];
                b[nt][1] = Bs[(kk + 4) * 136 + n];
            }
            #pragma unroll
            for (int mt = 0; mt < 4; mt++)
                #pragma unroll
                for (int nt = 0; nt < 8; nt++) {
                    asm volatile(
                        "mma.sync.aligned.m16n8k8.row.col.f32.tf32.tf32.f32 "
                        "{%0,%1,%2,%3}, {%4,%5,%6,%7}, {%8,%9}, {%0,%1,%2,%3};"
                        : "+f"(c[mt][nt][0]), "+f"(c[mt][nt][1]),
                          "+f"(c[mt][nt][2]), "+f"(c[mt][nt][3])
                        : "r"(a[mt][0]), "r"(a[mt][1]), "r"(a[mt][2]), "r"(a[mt][3]),
                          "r"(b[nt][0]), "r"(b[nt][1]));
                }
        }
    }

    #pragma unroll
    for (int mt = 0; mt < 4; mt++) {
        int row0 = bm + wm * 64 + mt * 16 + (lane >> 2);
        #pragma unroll
        for (int nt = 0; nt < 8; nt++) {
            int col = bn + wn * 64 + nt * 8 + (lane & 3) * 2;
            float b0 = bias[col], b1 = bias[col + 1];
            #pragma unroll
            for (int half = 0; half < 2; half++) {
                int row = row0 + half * 8;
                if (row < M) {
                    float v0 = c[mt][nt][half * 2 + 0] + b0;
                    float v1 = c[mt][nt][half * 2 + 1] + b1;
                    if (RELU)  { v0 = fmaxf(v0, 0.f); v1 = fmaxf(v1, 0.f); }
                    if (ROUND) { v0 = rnatf(v0); v1 = rnatf(v1); }
                    float* cp = C + (size_t)row * N + col;
                    cp[0] = v0; cp[1] = v1;
                }
            }
        }
    }
}

// ---------------- fused positional-encoding GEMM ----------------
// fvec[r,col] = rna(fvec[r,col] + relu(qp[r]@pe_w1+pe_b1) @ pe_w2 + pe_b2)
__global__ __launch_bounds__(256, 2) void pe_gemm(
    const float* __restrict__ qpos,    // [8][Q][3]
    const float* __restrict__ pew1,    // [3][256]
    const float* __restrict__ peb1,    // [256]
    const float* __restrict__ pew2,    // [256][128]
    const float* __restrict__ peb2,    // [128]
    float* __restrict__ C)             // fvec
{
    __shared__ uint32_t As[128 * 36];
    __shared__ uint32_t Bs[32 * 136];
    __shared__ float sw1[768];
    __shared__ float sb1[256];
    __shared__ float sxyz[128 * 3];

    const int tid  = threadIdx.x;
    const int lane = tid & 31;
    const int warp = tid >> 5;
    const int wm = warp >> 2;
    const int wn = warp & 3;
    const int bm = blockIdx.x * 128;

    sw1[tid] = pew1[tid]; sw1[tid + 256] = pew1[tid + 256]; sw1[tid + 512] = pew1[tid + 512];
    if (tid < 256) sb1[tid] = peb1[tid];
    if (tid < 128) {
        int r = bm + tid;
        int q = r >> 3, p = r & 7;
        const float* xp = qpos + ((size_t)p * QN + q) * 3;
        sxyz[tid * 3 + 0] = xp[0];
        sxyz[tid * 3 + 1] = xp[1];
        sxyz[tid * 3 + 2] = xp[2];
    }

    float c[4][4][4];
    #pragma unroll
    for (int i = 0; i < 4; i++)
        #pragma unroll
        for (int j = 0; j < 4; j++) {
            c[i][j][0] = 0.f; c[i][j][1] = 0.f; c[i][j][2] = 0.f; c[i][j][3] = 0.f;
        }

    const int am = tid >> 3, akq = tid & 7;
    const int bkr = tid >> 5, bnq = tid & 31;

    __syncthreads();

    for (int k0 = 0; k0 < 256; k0 += 32) {
        __syncthreads();
        #pragma unroll
        for (int i = 0; i < 4; i++) {
            int m = am + 32 * i;
            float x0 = sxyz[m * 3], x1 = sxyz[m * 3 + 1], x2 = sxyz[m * 3 + 2];
            uint32_t* p = &As[m * 36 + akq * 4];
            #pragma unroll
            for (int t = 0; t < 4; t++) {
                int j = k0 + akq * 4 + t;
                float h = sb1[j] + x0 * sw1[j] + x1 * sw1[256 + j] + x2 * sw1[512 + j];
                p[t] = f2tf(fmaxf(h, 0.f));
            }
        }
        #pragma unroll
        for (int i = 0; i < 4; i++) {
            float4 b4 = *(const float4*)(pew2 + (size_t)(k0 + bkr + 8 * i) * 128 + bnq * 4);
            uint32_t* p = &Bs[(bkr + 8 * i) * 136 + bnq * 4];
            p[0] = f2tf(b4.x); p[1] = f2tf(b4.y); p[2] = f2tf(b4.z); p[3] = f2tf(b4.w);
        }
        __syncthreads();

        #pragma unroll
        for (int kt = 0; kt < 4; kt++) {
            const int kk = kt * 8 + (lane & 3);
            uint32_t a[4][4], b[4][2];
            const int mrow = wm * 64 + (lane >> 2);
            #pragma unroll
            for (int mt = 0; mt < 4; mt++) {
                int m = mrow + mt * 16;
                a[mt][0] = As[m * 36 + kk];
                a[mt][1] = As[(m + 8) * 36 + kk];
                a[mt][2] = As[m * 36 + kk + 4];
                a[mt][3] = As[(m + 8) * 36 + kk + 4];
            }
            const int ncol = wn * 32 + (lane >> 2);
            #pragma unroll
            for (int nt = 0; nt < 4; nt++) {
                int n = ncol + nt * 8;
                b[nt][0] = Bs[kk * 136 + n];
                b[nt][1] = Bs[(kk + 4) * 136 + n];
            }
            #pragma unroll
            for (int mt = 0; mt < 4; mt++)
                #pragma unroll
                for (int nt = 0; nt < 4; nt++) {
                    asm volatile(
                        "mma.sync.aligned.m16n8k8.row.col.f32.tf32.tf32.f32 "
                        "{%0,%1,%2,%3}, {%4,%5,%6,%7}, {%8,%9}, {%0,%1,%2,%3};"
                        : "+f"(c[mt][nt][0]), "+f"(c[mt][nt][1]),
                          "+f"(c[mt][nt][2]), "+f"(c[mt][nt][3])
                        : "r"(a[mt][0]), "r"(a[mt][1]), "r"(a[mt][2]), "r"(a[mt][3]),
                          "r"(b[nt][0]), "r"(b[nt][1]));
                }
        }
    }

    #pragma unroll
    for (int mt = 0; mt < 4; mt++) {
        int row0 = bm + wm * 64 + mt * 16 + (lane >> 2);
        #pragma unroll
        for (int nt = 0; nt < 4; nt++) {
            int col = wn * 32 + nt * 8 + (lane & 3) * 2;
            float b0 = peb2[col], b1 = peb2[col + 1];
            #pragma unroll
            for (int half = 0; half < 2; half++) {
                int row = row0 + half * 8;
                float* cp = C + (size_t)row * 128 + col;
                cp[0] = rnatf(cp[0] + c[mt][nt][half * 2 + 0] + b0);
                cp[1] = rnatf(cp[1] + c[mt][nt][half * 2 + 1] + b1);
            }
        }
    }
}

// ---------------- final transpose: [Q][128] -> [128][Q] ----------------
__global__ void transpose_out_kernel(const float* __restrict__ in, float* __restrict__ out) {
    __shared__ float s[32][33];
    int q0 = blockIdx.x * 32, e0 = blockIdx.y * 32;
    int tx = threadIdx.x, ty = threadIdx.y;
    s[ty][tx] = in[(size_t)(q0 + ty) * 128 + (e0 + tx)];
    __syncthreads();
    out[(size_t)(e0 + ty) * QN + (q0 + tx)] = s[tx][ty];
}

// ---------------- launch ----------------
extern "C" void kernel_launch(void* const* d_in, const int* in_sizes, int n_in,
                              void* d_out, int out_size) {
    const float* feat0 = (const float*)d_in[0];
    const float* feat1 = (const float*)d_in[1];
    const float* feat2 = (const float*)d_in[2];
    const float* feat3 = (const float*)d_in[3];
    const float* query = (const float*)d_in[4];
    const float* qpos  = (const float*)d_in[5];
    const float* l2i   = (const float*)d_in[6];
    const float* Wsw   = (const float*)d_in[7];
    const float* bsw   = (const float*)d_in[8];
    const float* pew1  = (const float*)d_in[9];
    const float* peb1  = (const float*)d_in[10];
    const float* pew2  = (const float*)d_in[11];
    const float* peb2  = (const float*)d_in[12];
    const float* cw1   = (const float*)d_in[13];
    const float* cb1   = (const float*)d_in[14];
    const float* cw2   = (const float*)d_in[15];
    const float* cb2   = (const float*)d_in[16];
    const float* cw3   = (const float*)d_in[17];
    const float* cb3   = (const float*)d_in[18];
    const float* cw4   = (const float*)d_in[19];
    const float* cb4   = (const float*)d_in[20];
    float* out = (float*)d_out;

    float* fv;  cudaGetSymbolAddress((void**)&fv,  g_fvec);
    float* h1;  cudaGetSymbolAddress((void**)&h1,  g_h1);
    float* h2;  cudaGetSymbolAddress((void**)&h2,  g_h2);
    float* w1;  cudaGetSymbolAddress((void**)&w1,  g_w1);
    float* w2;  cudaGetSymbolAddress((void**)&w2,  g_w2);
    float* w3;  cudaGetSymbolAddress((void**)&w3,  g_w3);
    float* w4;  cudaGetSymbolAddress((void**)&w4,  g_w4);

    const size_t dsmem = (size_t)STG * NSTAGE * 4;   // 107.5 KB
    cudaFuncSetAttribute(mma_gemm5<1, 1>, cudaFuncAttributeMaxDynamicSharedMemorySize, (int)dsmem);
    cudaFuncSetAttribute(mma_gemm5<0, 0>, cudaFuncAttributeMaxDynamicSharedMemorySize, (int)dsmem);

    // launch 0: weight rounding (fused)
    const int RN = W1N + W2N + W3N + W4N;
    round_all_kernel<<<(RN + 255) / 256, 256>>>(cw1, cw2, cw3, cw4);

    // launch 1: feature transpose (fused, all levels)
    transpose_all_kernel<<<dim3(281, 4, 6), dim3(32, 32)>>>(feat0, feat1, feat2, feat3);

    // launch 2: sampling
    sample_kernel<<<QN, 128>>>(query, qpos, l2i, Wsw, bsw);

    // launch 3: fvec = rna(sampled + pos_emb)
    pe_gemm<<<QN * 8 / 128, 256>>>(qpos, pew1, peb1, pew2, peb2, fv);

    // launches 4-7: compressor GEMMs (launch 5 = gemm2 gets ncu-profiled)
    const int MB = (QN + 127) / 128; // 313
    mma_gemm5<1, 1><<<dim3(4, MB), 128, dsmem>>>(fv, w1, cb1, h1, QN, 1024, 512);
    mma_gemm5<1, 1><<<dim3(4, MB), 128, dsmem>>>(h1, w2, cb2, h2, QN, 512, 512);
    mma_gemm5<1, 1><<<dim3(4, MB), 128, dsmem>>>(h2, w3, cb3, h1, QN, 512, 512);
    mma_gemm5<0, 0><<<dim3(1, MB), 128, dsmem>>>(h1, w4, cb4, h2, QN, 512, 128);

    // launch 8: output transpose
    transpose_out_kernel<<<dim3(QN / 32, 4), dim3(32, 32)>>>(h2, out);
}